// round 17
// baseline (speedup 1.0000x reference)
#include <cuda_runtime.h>
#include <cuda_bf16.h>
#include <cstdint>
#include <math.h>

// Problem constants
#define BATCH 32768
#define SEQ   8
#define HEADS 8
#define HD    32
#define SCALE 0.17677669529663687f   // 1/sqrt(32)

// Scratch globals
__device__ __nv_bfloat16  g_qk[(size_t)BATCH * SEQ * 512];   // Q|K bf16 per token
__device__ float          g_v[(size_t)BATCH * SEQ * 256];    // V fp32 per token
__device__ __nv_bfloat16  g_w_hi[256 * 768];
__device__ __nv_bfloat16  g_w_lo[256 * 768];
__device__ __nv_bfloat16  g_wo_hi[256 * 256];
__device__ __nv_bfloat16  g_wo_lo[256 * 256];
__device__ __nv_bfloat16  g_pool_hi[(size_t)BATCH * 2 * 256];
__device__ __nv_bfloat16  g_pool_lo[(size_t)BATCH * 2 * 256];

// ---------------------------------------------------------------------------
// PTX helpers
// ---------------------------------------------------------------------------
__device__ __forceinline__ unsigned smem_u32(const void* p)
{
    return (unsigned)__cvta_generic_to_shared(p);
}

__device__ __forceinline__ void ldsm4(unsigned* r, unsigned a)
{
    asm volatile("ldmatrix.sync.aligned.m8n8.x4.shared.b16 {%0,%1,%2,%3},[%4];"
                 : "=r"(r[0]), "=r"(r[1]), "=r"(r[2]), "=r"(r[3]) : "r"(a));
}

__device__ __forceinline__ void ldsm4t(unsigned* r, unsigned a)
{
    asm volatile("ldmatrix.sync.aligned.m8n8.x4.trans.shared.b16 {%0,%1,%2,%3},[%4];"
                 : "=r"(r[0]), "=r"(r[1]), "=r"(r[2]), "=r"(r[3]) : "r"(a));
}

__device__ __forceinline__ void mma16816(float* d, const unsigned* a, const unsigned* b)
{
    asm volatile(
        "mma.sync.aligned.m16n8k16.row.col.f32.bf16.bf16.f32 "
        "{%0,%1,%2,%3},{%4,%5,%6,%7},{%8,%9},{%0,%1,%2,%3};"
        : "+f"(d[0]), "+f"(d[1]), "+f"(d[2]), "+f"(d[3])
        : "r"(a[0]), "r"(a[1]), "r"(a[2]), "r"(a[3]), "r"(b[0]), "r"(b[1]));
}

__device__ __forceinline__ void cpa16(unsigned dst, const void* src)
{
    asm volatile("cp.async.cg.shared.global [%0], [%1], 16;" :: "r"(dst), "l"(src));
}
__device__ __forceinline__ void cpa_commit()
{
    asm volatile("cp.async.commit_group;" ::: "memory");
}
__device__ __forceinline__ void cpa_wait1()
{
    asm volatile("cp.async.wait_group 1;" ::: "memory");
}

__device__ __forceinline__ unsigned pack_bf2(float x, float y)
{
    float2 f;
    f.x = x;
    f.y = y;
    __nv_bfloat162 b = __float22bfloat162_rn(f);
    return *reinterpret_cast<unsigned*>(&b);
}

// ---------------------------------------------------------------------------
// Common tile constants
// ---------------------------------------------------------------------------
#define BKK 32
#define STAGES 3
#define A_LD 40          // bf16 A stride (GEMM2)
#define A_LDF 40         // fp32 A stride (GEMM1) — conflict-free LDS.64 phases
#define B_LD 136
#define A_STAGE_ELN (128 * A_LD)
#define A_STAGE_F   (128 * A_LDF)
#define B_STAGE_ELN (32 * B_LD)
#define GEMM_SMEM_BYTES ((2 * STAGES * A_STAGE_ELN + 2 * STAGES * B_STAGE_ELN) * 2)
#define QKV_SMEM_BYTES (STAGES * A_STAGE_F * 4 + 2 * STAGES * B_STAGE_ELN * 2)

// ---------------------------------------------------------------------------
// GEMM1 (fused x split): reads x fp32, builds bf16 fragments in-register.
// Q,K: 1-term (hh).  V: 3-term (hh+hl+lh), lo derived from fp32 in regs.
// Epilogue: Q,K -> bf16 g_qk; V -> fp32 g_v.
// ---------------------------------------------------------------------------
__global__ __launch_bounds__(256)
void gemm_qkv_kernel(const float* __restrict__ X,
                     const __nv_bfloat16* __restrict__ Whi,
                     const __nv_bfloat16* __restrict__ Wlo,
                     const float* __restrict__ b0, const float* __restrict__ b1,
                     const float* __restrict__ b2,
                     __nv_bfloat16* __restrict__ QK,
                     float* __restrict__ Vout)
{
    extern __shared__ char smem_raw[];
    float* const saF = reinterpret_cast<float*>(smem_raw);
    __nv_bfloat16* const sbH =
        reinterpret_cast<__nv_bfloat16*>(smem_raw + STAGES * A_STAGE_F * 4);
    __nv_bfloat16* const sbL = sbH + STAGES * B_STAGE_ELN;

    const int tid  = threadIdx.x;
    const int lane = tid & 31;
    const int wid  = tid >> 5;

    const long row0 = (long)blockIdx.y * 128;
    const int  col0 = blockIdx.x * 128;
    const int  sel  = col0 >> 8;
    const float* __restrict__ bp = (sel == 0) ? b0 : ((sel == 1) ? b1 : b2);
    const int wcol0 = col0 & 255;

    const bool vterm = (sel == 2);    // V: full 3-term; Q,K: 1-term

    const int wm = (wid >> 2) * 64;
    const int wn = (wid & 3) * 32;

    float acc[4][4][4];
    #pragma unroll
    for (int i = 0; i < 4; i++) {
        #pragma unroll
        for (int j = 0; j < 4; j++) {
            #pragma unroll
            for (int k = 0; k < 4; k++) {
                acc[i][j][k] = 0.f;
            }
        }
    }

    auto load_stage = [&](int chunk) {
        const int st = chunk % STAGES;
        const int k0 = chunk * BKK;
        // A: 128x32 fp32 = 1024 x 16B, 4 per thread
        #pragma unroll
        for (int t = 0; t < 4; t++) {
            const int id = t * 256 + tid;
            const int r  = id >> 3;
            const int c4 = (id & 7) * 4;
            cpa16(smem_u32(saF + st * A_STAGE_F + r * A_LDF + c4),
                  X + (row0 + r) * 256 + k0 + c4);
        }
        // B: bf16 hi (+lo for V)
        #pragma unroll
        for (int t = 0; t < 2; t++) {
            const int id = t * 256 + tid;
            const int r  = id >> 4;
            const int c8 = (id & 15) * 8;
            cpa16(smem_u32(sbH + st * B_STAGE_ELN + r * B_LD + c8),
                  Whi + (size_t)(k0 + r) * 768 + col0 + c8);
            if (vterm) {
                cpa16(smem_u32(sbL + st * B_STAGE_ELN + r * B_LD + c8),
                      Wlo + (size_t)(k0 + r) * 768 + col0 + c8);
            }
        }
    };

    load_stage(0);
    cpa_commit();
    load_stage(1);
    cpa_commit();

    const int gr = lane >> 2;          // fragment row within 8
    const int gc = (lane & 3) * 2;     // fragment col pair base

    #pragma unroll 1
    for (int ch = 0; ch < 8; ch++) {
        cpa_wait1();
        __syncthreads();

        if (ch + 2 < 8) {
            load_stage(ch + 2);
        }
        cpa_commit();

        const int st = ch % STAGES;
        const float* aFs = saF + st * A_STAGE_F;
        const __nv_bfloat16* bHs = sbH + st * B_STAGE_ELN;
        const __nv_bfloat16* bLs = sbL + st * B_STAGE_ELN;

        #pragma unroll
        for (int ks = 0; ks < BKK; ks += 16) {
            unsigned aHf[4][4];
            unsigned aLf[4][4];
            unsigned bHf[2][4];
            unsigned bLf[2][4];

            // Build A fragments from fp32 smem (m16n8k16 layout):
            //   reg0: (row gr,   cols gc,gc+1)   reg1: (row gr+8, same)
            //   reg2: (row gr,   cols gc+8,+9)   reg3: (row gr+8, same)
            #pragma unroll
            for (int mt = 0; mt < 4; mt++) {
                const float* base = aFs + (wm + mt * 16 + gr) * A_LDF + ks + gc;
                const float2 x00 = *reinterpret_cast<const float2*>(base);
                const float2 x10 = *reinterpret_cast<const float2*>(base + 8 * A_LDF);
                const float2 x01 = *reinterpret_cast<const float2*>(base + 8);
                const float2 x11 = *reinterpret_cast<const float2*>(base + 8 * A_LDF + 8);
                aHf[mt][0] = pack_bf2(x00.x, x00.y);
                aHf[mt][1] = pack_bf2(x10.x, x10.y);
                aHf[mt][2] = pack_bf2(x01.x, x01.y);
                aHf[mt][3] = pack_bf2(x11.x, x11.y);
                if (vterm) {
                    const __nv_bfloat162* h = reinterpret_cast<const __nv_bfloat162*>(aHf[mt]);
                    float2 h0 = __bfloat1622float2(h[0]);
                    float2 h1 = __bfloat1622float2(h[1]);
                    float2 h2 = __bfloat1622float2(h[2]);
                    float2 h3 = __bfloat1622float2(h[3]);
                    aLf[mt][0] = pack_bf2(x00.x - h0.x, x00.y - h0.y);
                    aLf[mt][1] = pack_bf2(x10.x - h1.x, x10.y - h1.y);
                    aLf[mt][2] = pack_bf2(x01.x - h2.x, x01.y - h2.y);
                    aLf[mt][3] = pack_bf2(x11.x - h3.x, x11.y - h3.y);
                }
            }

            const int brow = ks + (lane & 15);
            #pragma unroll
            for (int nt2 = 0; nt2 < 2; nt2++) {
                const int bcol = wn + nt2 * 16 + (lane >> 4) * 8;
                ldsm4t(bHf[nt2], smem_u32(bHs + brow * B_LD + bcol));
            }
            if (vterm) {
                #pragma unroll
                for (int nt2 = 0; nt2 < 2; nt2++) {
                    const int bcol = wn + nt2 * 16 + (lane >> 4) * 8;
                    ldsm4t(bLf[nt2], smem_u32(bLs + brow * B_LD + bcol));
                }
            }

            #pragma unroll
            for (int mt = 0; mt < 4; mt++) {
                #pragma unroll
                for (int nt = 0; nt < 4; nt++) {
                    mma16816(acc[mt][nt], aHf[mt], &bHf[nt >> 1][(nt & 1) * 2]);  // hi*hi
                }
            }
            if (vterm) {
                #pragma unroll
                for (int mt = 0; mt < 4; mt++) {
                    #pragma unroll
                    for (int nt = 0; nt < 4; nt++) {
                        mma16816(acc[mt][nt], aHf[mt], &bLf[nt >> 1][(nt & 1) * 2]);  // hi*lo
                    }
                }
                #pragma unroll
                for (int mt = 0; mt < 4; mt++) {
                    #pragma unroll
                    for (int nt = 0; nt < 4; nt++) {
                        mma16816(acc[mt][nt], aLf[mt], &bHf[nt >> 1][(nt & 1) * 2]);  // lo*hi
                    }
                }
            }
        }
    }

    #pragma unroll
    for (int mt = 0; mt < 4; mt++) {
        const long gr2 = row0 + wm + mt * 16 + (lane >> 2);
        #pragma unroll
        for (int nt = 0; nt < 4; nt++) {
            const int cloc = wn + nt * 8 + (lane & 3) * 2;
            const int cw   = wcol0 + cloc;
            const float bz0 = bp[cw];
            const float bz1 = bp[cw + 1];
            const float v00 = acc[mt][nt][0] + bz0;
            const float v01 = acc[mt][nt][1] + bz1;
            const float v10 = acc[mt][nt][2] + bz0;
            const float v11 = acc[mt][nt][3] + bz1;

            if (sel < 2) {
                __nv_bfloat162 p0;
                p0.x = __float2bfloat16_rn(v00);
                p0.y = __float2bfloat16_rn(v01);
                __nv_bfloat162 p1;
                p1.x = __float2bfloat16_rn(v10);
                p1.y = __float2bfloat16_rn(v11);
                *reinterpret_cast<__nv_bfloat162*>(QK + gr2 * 512 + sel * 256 + cw) = p0;
                *reinterpret_cast<__nv_bfloat162*>(QK + (gr2 + 8) * 512 + sel * 256 + cw) = p1;
            } else {
                float2 f0;
                f0.x = v00;
                f0.y = v01;
                float2 f1;
                f1.x = v10;
                f1.y = v11;
                *reinterpret_cast<float2*>(Vout + gr2 * 256 + cw) = f0;
                *reinterpret_cast<float2*>(Vout + (gr2 + 8) * 256 + cw) = f1;
            }
        }
    }
}

// ---------------------------------------------------------------------------
// GEMM2 (round-16 kernel, pre-split bf16 A): out = pool @ Wo + bias, 3-term
// ---------------------------------------------------------------------------
__global__ __launch_bounds__(256)
void gemm_bf16_kernel(const __nv_bfloat16* __restrict__ Ahi,
                      const __nv_bfloat16* __restrict__ Alo,
                      const __nv_bfloat16* __restrict__ Whi,
                      const __nv_bfloat16* __restrict__ Wlo,
                      const float* __restrict__ bias,
                      float* __restrict__ C)
{
    extern __shared__ __nv_bfloat16 smem[];
    __nv_bfloat16* const saH = smem;
    __nv_bfloat16* const saL = saH + STAGES * A_STAGE_ELN;
    __nv_bfloat16* const sbH = saL + STAGES * A_STAGE_ELN;
    __nv_bfloat16* const sbL = sbH + STAGES * B_STAGE_ELN;

    const int tid  = threadIdx.x;
    const int lane = tid & 31;
    const int wid  = tid >> 5;

    const long row0 = (long)blockIdx.y * 128;
    const int  col0 = blockIdx.x * 128;

    const int wm = (wid >> 2) * 64;
    const int wn = (wid & 3) * 32;

    float acc[4][4][4];
    #pragma unroll
    for (int i = 0; i < 4; i++) {
        #pragma unroll
        for (int j = 0; j < 4; j++) {
            #pragma unroll
            for (int k = 0; k < 4; k++) {
                acc[i][j][k] = 0.f;
            }
        }
    }

    auto load_stage = [&](int chunk) {
        const int st = chunk % STAGES;
        const int k0 = chunk * BKK;
        #pragma unroll
        for (int t = 0; t < 2; t++) {
            const int id = t * 256 + tid;
            const int r  = id >> 2;
            const int c8 = (id & 3) * 8;
            cpa16(smem_u32(saH + st * A_STAGE_ELN + r * A_LD + c8),
                  Ahi + (row0 + r) * 256 + k0 + c8);
            cpa16(smem_u32(saL + st * A_STAGE_ELN + r * A_LD + c8),
                  Alo + (row0 + r) * 256 + k0 + c8);
        }
        #pragma unroll
        for (int t = 0; t < 2; t++) {
            const int id = t * 256 + tid;
            const int r  = id >> 4;
            const int c8 = (id & 15) * 8;
            cpa16(smem_u32(sbH + st * B_STAGE_ELN + r * B_LD + c8),
                  Whi + (size_t)(k0 + r) * 256 + col0 + c8);
            cpa16(smem_u32(sbL + st * B_STAGE_ELN + r * B_LD + c8),
                  Wlo + (size_t)(k0 + r) * 256 + col0 + c8);
        }
    };

    load_stage(0);
    cpa_commit();
    load_stage(1);
    cpa_commit();

    #pragma unroll 1
    for (int ch = 0; ch < 8; ch++) {
        cpa_wait1();
        __syncthreads();

        if (ch + 2 < 8) {
            load_stage(ch + 2);
        }
        cpa_commit();

        const int st = ch % STAGES;
        const __nv_bfloat16* aHs = saH + st * A_STAGE_ELN;
        const __nv_bfloat16* aLs = saL + st * A_STAGE_ELN;
        const __nv_bfloat16* bHs = sbH + st * B_STAGE_ELN;
        const __nv_bfloat16* bLs = sbL + st * B_STAGE_ELN;

        #pragma unroll
        for (int ks = 0; ks < BKK; ks += 16) {
            unsigned aHf[4][4];
            unsigned aLf[4][4];
            unsigned bHf[2][4];
            unsigned bLf[2][4];

            const int arow = lane & 15;
            const int acol = ks + (lane >> 4) * 8;
            #pragma unroll
            for (int mt = 0; mt < 4; mt++) {
                ldsm4(aHf[mt], smem_u32(aHs + (wm + mt * 16 + arow) * A_LD + acol));
                ldsm4(aLf[mt], smem_u32(aLs + (wm + mt * 16 + arow) * A_LD + acol));
            }
            const int brow = ks + (lane & 15);
            #pragma unroll
            for (int nt2 = 0; nt2 < 2; nt2++) {
                const int bcol = wn + nt2 * 16 + (lane >> 4) * 8;
                ldsm4t(bHf[nt2], smem_u32(bHs + brow * B_LD + bcol));
                ldsm4t(bLf[nt2], smem_u32(bLs + brow * B_LD + bcol));
            }
            #pragma unroll
            for (int mt = 0; mt < 4; mt++) {
                #pragma unroll
                for (int nt = 0; nt < 4; nt++) {
                    mma16816(acc[mt][nt], aHf[mt], &bHf[nt >> 1][(nt & 1) * 2]);
                }
            }
            #pragma unroll
            for (int mt = 0; mt < 4; mt++) {
                #pragma unroll
                for (int nt = 0; nt < 4; nt++) {
                    mma16816(acc[mt][nt], aHf[mt], &bLf[nt >> 1][(nt & 1) * 2]);
                }
            }
            #pragma unroll
            for (int mt = 0; mt < 4; mt++) {
                #pragma unroll
                for (int nt = 0; nt < 4; nt++) {
                    mma16816(acc[mt][nt], aLf[mt], &bHf[nt >> 1][(nt & 1) * 2]);
                }
            }
        }
    }

    #pragma unroll
    for (int mt = 0; mt < 4; mt++) {
        const long gr = row0 + wm + mt * 16 + (lane >> 2);
        #pragma unroll
        for (int nt = 0; nt < 4; nt++) {
            const int cloc = wn + nt * 8 + (lane & 3) * 2;
            const float bz0 = bias[col0 + cloc];
            const float bz1 = bias[col0 + cloc + 1];
            float2 f0;
            f0.x = acc[mt][nt][0] + bz0;
            f0.y = acc[mt][nt][1] + bz1;
            float2 f1;
            f1.x = acc[mt][nt][2] + bz0;
            f1.y = acc[mt][nt][3] + bz1;
            *reinterpret_cast<float2*>(C + gr * 256 + col0 + cloc) = f0;
            *reinterpret_cast<float2*>(C + (gr + 8) * 256 + col0 + cloc) = f1;
        }
    }
}

// ---------------------------------------------------------------------------
// Weight hi/lo conversion
// ---------------------------------------------------------------------------
__global__ __launch_bounds__(256)
void convert_w_kernel(const float* __restrict__ Wq, const float* __restrict__ Wk,
                      const float* __restrict__ Wv, const float* __restrict__ Wo)
{
    const int k = blockIdx.x;
    const int n = threadIdx.x;
    {
        const float v = Wq[k * 256 + n];
        __nv_bfloat16 h = __float2bfloat16_rn(v);
        g_w_hi[k * 768 + n] = h;
        g_w_lo[k * 768 + n] = __float2bfloat16_rn(v - __bfloat162float(h));
    }
    {
        const float v = Wk[k * 256 + n];
        __nv_bfloat16 h = __float2bfloat16_rn(v);
        g_w_hi[k * 768 + 256 + n] = h;
        g_w_lo[k * 768 + 256 + n] = __float2bfloat16_rn(v - __bfloat162float(h));
    }
    {
        const float v = Wv[k * 256 + n];
        __nv_bfloat16 h = __float2bfloat16_rn(v);
        g_w_hi[k * 768 + 512 + n] = h;
        g_w_lo[k * 768 + 512 + n] = __float2bfloat16_rn(v - __bfloat162float(h));
    }
    {
        const float v = Wo[k * 256 + n];
        __nv_bfloat16 h = __float2bfloat16_rn(v);
        g_wo_hi[k * 256 + n] = h;
        g_wo_lo[k * 256 + n] = __float2bfloat16_rn(v - __bfloat162float(h));
    }
}

// ---------------------------------------------------------------------------
// attn v5 (round-15/16, measured 180-181us)
// ---------------------------------------------------------------------------
#define QKV_LDS 772

__global__ __launch_bounds__(256)
void attn_kernel(const float* __restrict__ e,
                 const float* __restrict__ Wbias,  const float* __restrict__ bbias,
                 const float* __restrict__ Wgate,  const float* __restrict__ bgate,
                 const float* __restrict__ Wscale, const float* __restrict__ bscale,
                 const float* __restrict__ Wshift, const float* __restrict__ bshift,
                 const float* __restrict__ Whs,    const float* __restrict__ bhs)
{
    __shared__ float sqkv[SEQ * QKV_LDS];
    __shared__ __align__(16) float sA[HEADS][SEQ][8];

    const int b    = blockIdx.x;
    const int tid  = threadIdx.x;
    const int h    = tid >> 5;
    const int lane = tid & 31;

    const float e0 = e[b * 2 + 0];
    const float e1 = e[b * 2 + 1];

    {
        const uint4* __restrict__ qk4 =
            reinterpret_cast<const uint4*>(g_qk + (size_t)b * SEQ * 512);
        #pragma unroll
        for (int j = 0; j < 2; j++) {
            const int i4   = j * 256 + tid;
            const int base = i4 * 8;
            const int t    = base >> 9;
            const int col  = base & 511;
            const uint4 raw = qk4[i4];
            const __nv_bfloat162* bp2 = reinterpret_cast<const __nv_bfloat162*>(&raw);
            float2 f0 = __bfloat1622float2(bp2[0]);
            float2 f1 = __bfloat1622float2(bp2[1]);
            float2 f2 = __bfloat1622float2(bp2[2]);
            float2 f3 = __bfloat1622float2(bp2[3]);
            float4 o0;
            o0.x = f0.x; o0.y = f0.y; o0.z = f1.x; o0.w = f1.y;
            float4 o1;
            o1.x = f2.x; o1.y = f2.y; o1.z = f3.x; o1.w = f3.y;
            *reinterpret_cast<float4*>(&sqkv[t * QKV_LDS + col])     = o0;
            *reinterpret_cast<float4*>(&sqkv[t * QKV_LDS + col + 4]) = o1;
        }
    }
    {
        const float4* __restrict__ v4 =
            reinterpret_cast<const float4*>(g_v + (size_t)b * SEQ * 256);
        #pragma unroll
        for (int j = 0; j < 2; j++) {
            const int i4   = j * 256 + tid;
            const int base = i4 * 4;
            const int t    = base >> 8;
            const int col  = base & 255;
            *reinterpret_cast<float4*>(&sqkv[t * QKV_LDS + 512 + col]) = v4[i4];
        }
    }

    const float eb = e0 * Wbias[h] + e1 * Wbias[8 + h] + bbias[h];
    const float hs = tanhf(e0 * Whs[h] + e1 * Whs[8 + h] + bhs[h]);
    const float score_mul = SCALE * (1.f + hs);

    const int c = tid;
    const float gate = 1.f / (1.f + expf(-(e0 * Wgate[c]  + e1 * Wgate[256 + c]  + bgate[c])));
    const float scl  = tanhf(        e0 * Wscale[c] + e1 * Wscale[256 + c] + bscale[c]);
    const float shf  =               e0 * Wshift[c] + e1 * Wshift[256 + c] + bshift[c];
    const float g2 = gate * (1.f + scl);
    const float s2 = shf * gate;

    __syncthreads();

    const float* __restrict__ Qb = &sqkv[h * 32];
    const float* __restrict__ Kb = &sqkv[256 + h * 32];
    const float* __restrict__ Vb = &sqkv[512 + h * 32];

    const int s0 = lane >> 3;
    const int s1 = s0 + 4;
    const int t  = lane & 7;
    float a0 = 0.f;
    float a1 = 0.f;
    #pragma unroll
    for (int d = 0; d < HD; d += 4) {
        const float4 kv = *reinterpret_cast<const float4*>(Kb + t * QKV_LDS + d);
        const float4 q0 = *reinterpret_cast<const float4*>(Qb + s0 * QKV_LDS + d);
        const float4 q1 = *reinterpret_cast<const float4*>(Qb + s1 * QKV_LDS + d);
        a0 = fmaf(q0.x, kv.x, a0);
        a0 = fmaf(q0.y, kv.y, a0);
        a0 = fmaf(q0.z, kv.z, a0);
        a0 = fmaf(q0.w, kv.w, a0);
        a1 = fmaf(q1.x, kv.x, a1);
        a1 = fmaf(q1.y, kv.y, a1);
        a1 = fmaf(q1.z, kv.z, a1);
        a1 = fmaf(q1.w, kv.w, a1);
    }
    a0 *= score_mul;
    a1 *= score_mul;
    if (t == s0 + 4) {
        a0 += eb;
    }
    if (t == s1 - 4) {
        a1 += eb;
    }

    float sc[2];
    sc[0] = a0;
    sc[1] = a1;
    #pragma unroll
    for (int p = 0; p < 2; p++) {
        float mx = sc[p];
        #pragma unroll
        for (int o = 4; o >= 1; o >>= 1) {
            mx = fmaxf(mx, __shfl_xor_sync(0xffffffffu, mx, o));
        }
        float ex = __expf(sc[p] - mx);
        float sm = ex;
        #pragma unroll
        for (int o = 4; o >= 1; o >>= 1) {
            sm += __shfl_xor_sync(0xffffffffu, sm, o);
        }
        sc[p] = ex / sm;
    }

    sA[h][s0][t] = sc[0];
    sA[h][s1][t] = sc[1];
    __syncwarp();

    float vreg[SEQ];
    #pragma unroll
    for (int tt = 0; tt < SEQ; tt++) {
        vreg[tt] = Vb[tt * QKV_LDS + lane];
    }

    float o[SEQ];
    #pragma unroll
    for (int s = 0; s < SEQ; s++) {
        const float4 w0 = *reinterpret_cast<const float4*>(&sA[h][s][0]);
        const float4 w1 = *reinterpret_cast<const float4*>(&sA[h][s][4]);
        float acc;
        acc = w0.x * vreg[0];
        acc = fmaf(w0.y, vreg[1], acc);
        acc = fmaf(w0.z, vreg[2], acc);
        acc = fmaf(w0.w, vreg[3], acc);
        acc = fmaf(w1.x, vreg[4], acc);
        acc = fmaf(w1.y, vreg[5], acc);
        acc = fmaf(w1.z, vreg[6], acc);
        acc = fmaf(w1.w, vreg[7], acc);
        o[s] = acc;
    }
    float p0 = (o[0] + o[1] + o[2] + o[3]) * 0.25f;
    float p1 = (o[4] + o[5] + o[6] + o[7]) * 0.25f;
    p0 = p0 * g2 + s2;
    p1 = p1 * g2 + s2;

    const long i0 = ((long)b * 2 + 0) * 256 + c;
    const long i1 = ((long)b * 2 + 1) * 256 + c;
    __nv_bfloat16 h0 = __float2bfloat16_rn(p0);
    __nv_bfloat16 h1 = __float2bfloat16_rn(p1);
    g_pool_hi[i0] = h0;
    g_pool_lo[i0] = __float2bfloat16_rn(p0 - __bfloat162float(h0));
    g_pool_hi[i1] = h1;
    g_pool_lo[i1] = __float2bfloat16_rn(p1 - __bfloat162float(h1));
}

// ---------------------------------------------------------------------------
extern "C" void kernel_launch(void* const* d_in, const int* in_sizes, int n_in,
                              void* d_out, int out_size)
{
    const float* x      = (const float*)d_in[0];
    const float* e      = (const float*)d_in[1];
    const float* Wq     = (const float*)d_in[2];
    const float* bq     = (const float*)d_in[3];
    const float* Wk     = (const float*)d_in[4];
    const float* bk     = (const float*)d_in[5];
    const float* Wv     = (const float*)d_in[6];
    const float* bv     = (const float*)d_in[7];
    const float* Wo     = (const float*)d_in[8];
    const float* bo     = (const float*)d_in[9];
    const float* Wbias  = (const float*)d_in[10];
    const float* bbias  = (const float*)d_in[11];
    const float* Wgate  = (const float*)d_in[12];
    const float* bgate  = (const float*)d_in[13];
    const float* Wscale = (const float*)d_in[14];
    const float* bscale = (const float*)d_in[15];
    const float* Wshift = (const float*)d_in[16];
    const float* bshift = (const float*)d_in[17];
    const float* Whs    = (const float*)d_in[18];
    const float* bhs    = (const float*)d_in[19];
    float* out = (float*)d_out;

    __nv_bfloat16 *qk_p = nullptr;
    float *v_p = nullptr;
    __nv_bfloat16 *whi_p = nullptr, *wlo_p = nullptr;
    __nv_bfloat16 *wohi_p = nullptr, *wolo_p = nullptr;
    __nv_bfloat16 *phi_p = nullptr, *plo_p = nullptr;
    cudaGetSymbolAddress((void**)&qk_p,   g_qk);
    cudaGetSymbolAddress((void**)&v_p,    g_v);
    cudaGetSymbolAddress((void**)&whi_p,  g_w_hi);
    cudaGetSymbolAddress((void**)&wlo_p,  g_w_lo);
    cudaGetSymbolAddress((void**)&wohi_p, g_wo_hi);
    cudaGetSymbolAddress((void**)&wolo_p, g_wo_lo);
    cudaGetSymbolAddress((void**)&phi_p,  g_pool_hi);
    cudaGetSymbolAddress((void**)&plo_p,  g_pool_lo);

    cudaFuncSetAttribute(gemm_qkv_kernel,
                         cudaFuncAttributeMaxDynamicSharedMemorySize, QKV_SMEM_BYTES);
    cudaFuncSetAttribute(gemm_bf16_kernel,
                         cudaFuncAttributeMaxDynamicSharedMemorySize, GEMM_SMEM_BYTES);

    // 0) weight conversion only (x conversion fused into GEMM1)
    convert_w_kernel<<<256, 256>>>(Wq, Wk, Wv, Wo);

    // 1) QKV projection (fused fp32->bf16 split): Q,K 1-term; V 3-term
    {
        dim3 grid(6, 2048);
        gemm_qkv_kernel<<<grid, 256, QKV_SMEM_BYTES>>>(
            x, whi_p, wlo_p, bq, bk, bv, qk_p, v_p);
    }

    // 2) Modulation + attention + pooling (emits pool hi/lo bf16)
    attn_kernel<<<BATCH, 256>>>(e, Wbias, bbias, Wgate, bgate,
                                Wscale, bscale, Wshift, bshift, Whs, bhs);

    // 3) Output projection: full 3-term
    {
        dim3 grid(2, 512);
        gemm_bf16_kernel<<<grid, 256, GEMM_SMEM_BYTES>>>(
            phi_p, plo_p, wohi_p, wolo_p, bo, out);
    }
}